// round 4
// baseline (speedup 1.0000x reference)
#include <cuda_runtime.h>
#include <cuda_bf16.h>
#include <cstdint>

#define N_ANCH   2000000
#define N_GRP    (N_ANCH / 4)      // 500000 uint4 groups
#define K_SEL    2000
#define OUT_ROWS 1000
#define IMG_SZ   800.0f
#define MIN_SZ   16.0f
#define NMS_TH   0.7f
#define NBIN     65536

#define CTL_BIN    0
#define CTL_NCAND  1
#define CTL_NPAIRS 2

// -------- device scratch --------
__device__ unsigned int       g_keys[N_ANCH];          // 8 MB
__device__ unsigned int       g_hist[NBIN];            // 256 KB, value-uniform bins
__device__ unsigned int       g_ctl[16];
__device__ unsigned long long g_cand[8192];
__device__ float4             g_boxes[K_SEL];
__device__ unsigned char      g_validk[K_SEL];
__device__ unsigned int       g_pairs[2000000];

// -------- decode helper (matches reference math) --------
__device__ __forceinline__ float4 decode_box(float4 a, float4 l) {
    float w  = a.z - a.x;
    float h  = a.w - a.y;
    float cx = a.x + 0.5f * w;
    float cy = a.y + 0.5f * h;
    float pcx = cx + l.x * w;
    float pcy = cy + l.y * h;
    float pw  = w * expf(l.z);
    float ph  = h * expf(l.w);
    float x1 = fminf(fmaxf(pcx - 0.5f * pw, 0.0f), IMG_SZ);
    float y1 = fminf(fmaxf(pcy - 0.5f * ph, 0.0f), IMG_SZ);
    float x2 = fminf(fmaxf(pcx + 0.5f * pw, 0.0f), IMG_SZ);
    float y2 = fminf(fmaxf(pcy + 0.5f * ph, 0.0f), IMG_SZ);
    return make_float4(x1, y1, x2, y2);
}

// value-uniform bin from key (key = float_bits(score)+1, score in [0,1))
__device__ __forceinline__ unsigned int key_bin(unsigned int key) {
    float s = __uint_as_float(key - 1u);
    unsigned int b = (unsigned int)(s * 65536.0f);
    return b > 65535u ? 65535u : b;
}

// -------- K0: zero hist + ctl --------
__global__ void k_zero() {
    int i = blockIdx.x * blockDim.x + threadIdx.x;
    ((uint4*)g_hist)[i] = make_uint4(0u, 0u, 0u, 0u);   // 64 blocks * 256 = 16384 uint4
    if (i < 16) g_ctl[i] = 0u;
}

// -------- K1: decode + key + uniform histogram --------
__global__ void __launch_bounds__(256) k_decode(const float4* __restrict__ locs,
                                                const float4* __restrict__ scores4,
                                                const float4* __restrict__ anchors) {
    int g = blockIdx.x * blockDim.x + threadIdx.x;
    if (g >= N_GRP) return;
    float4 s4 = scores4[g];
    float4 a0 = anchors[4*g+0], a1 = anchors[4*g+1], a2 = anchors[4*g+2], a3 = anchors[4*g+3];
    float4 l0 = locs[4*g+0],    l1 = locs[4*g+1],    l2 = locs[4*g+2],    l3 = locs[4*g+3];
    float4 d0 = decode_box(a0, l0);
    float4 d1 = decode_box(a1, l1);
    float4 d2 = decode_box(a2, l2);
    float4 d3 = decode_box(a3, l3);
    uint4 k4;
    k4.x = ((d0.z-d0.x >= MIN_SZ) && (d0.w-d0.y >= MIN_SZ)) ? (__float_as_uint(s4.x)+1u) : 0u;
    k4.y = ((d1.z-d1.x >= MIN_SZ) && (d1.w-d1.y >= MIN_SZ)) ? (__float_as_uint(s4.y)+1u) : 0u;
    k4.z = ((d2.z-d2.x >= MIN_SZ) && (d2.w-d2.y >= MIN_SZ)) ? (__float_as_uint(s4.z)+1u) : 0u;
    k4.w = ((d3.z-d3.x >= MIN_SZ) && (d3.w-d3.y >= MIN_SZ)) ? (__float_as_uint(s4.w)+1u) : 0u;
    ((uint4*)g_keys)[g] = k4;
    if (k4.x) atomicAdd(&g_hist[key_bin(k4.x)], 1u);
    if (k4.y) atomicAdd(&g_hist[key_bin(k4.y)], 1u);
    if (k4.z) atomicAdd(&g_hist[key_bin(k4.z)], 1u);
    if (k4.w) atomicAdd(&g_hist[key_bin(k4.w)], 1u);
}

// -------- K2: find threshold bin B = max{b : suffix_count(b) >= K_SEL} --------
__global__ void k_select() {
    __shared__ unsigned int A[1024], B[1024];
    int t = threadIdx.x;
    // chunk t covers bins [t*64, t*64+64)
    unsigned int s = 0;
    const unsigned int* h = &g_hist[t * 64];
    #pragma unroll 8
    for (int i = 0; i < 64; i++) s += h[i];
    A[t] = s;
    __syncthreads();
    // inclusive suffix sum over 1024 chunk sums (Hillis-Steele, double buffer)
    unsigned int* src = A; unsigned int* dst = B;
    for (int d = 1; d < 1024; d <<= 1) {
        dst[t] = src[t] + (t + d < 1024 ? src[t + d] : 0u);
        __syncthreads();
        unsigned int* tmp = src; src = dst; dst = tmp;
    }
    unsigned int suf     = src[t];
    unsigned int sufNext = (t == 1023) ? 0u : src[t + 1];
    if (suf >= (unsigned)K_SEL && sufNext < (unsigned)K_SEL) {
        // winner chunk: walk bins from top down
        unsigned int running = sufNext;
        for (int i = 63; i >= 0; i--) {
            running += h[i];
            if (running >= (unsigned)K_SEL) { g_ctl[CTL_BIN] = (unsigned)(t * 64 + i); break; }
        }
    }
}

// -------- K3: collect candidates with bin >= B (MLP-2, single pass) --------
__global__ void __launch_bounds__(256) k_collect() {
    unsigned int Bth = g_ctl[CTL_BIN];
    int g = (blockIdx.x * blockDim.x + threadIdx.x) * 2;
    if (g >= N_GRP) return;
    const uint4* keys4 = (const uint4*)g_keys;
    uint4 ka = keys4[g];
    uint4 kb = keys4[g + 1];
    unsigned int kk[8] = {ka.x, ka.y, ka.z, ka.w, kb.x, kb.y, kb.z, kb.w};
    #pragma unroll
    for (int c = 0; c < 8; c++) {
        unsigned int key = kk[c];
        if (key != 0u && key_bin(key) >= Bth) {
            unsigned int i = (unsigned)(4 * g + c);
            unsigned int pos = atomicAdd(&g_ctl[CTL_NCAND], 1u);
            if (pos < 8192u)
                g_cand[pos] = ((unsigned long long)key << 32) | (unsigned int)(~i);
        }
    }
}

// -------- K4: sort candidates (adaptive 2048/4096), build top-2000 boxes --------
__global__ void k_finalize(const float4* __restrict__ locs,
                           const float4* __restrict__ anchors) {
    __shared__ unsigned long long sv[4096];
    __shared__ int snc;
    int tid = threadIdx.x;
    unsigned int n = g_ctl[CTL_NCAND];
    if (n > 8192u) n = 8192u;
    if (tid == 0) snc = 0;
    for (int i = tid; i < 4096; i += blockDim.x) sv[i] = 0ULL;
    __syncthreads();
    // load candidates (n is ~2030; clamp into 4096 slots)
    for (int i = tid; i < (int)n; i += blockDim.x) {
        int p = atomicAdd(&snc, 1);
        if (p < 4096) sv[p] = g_cand[i];
    }
    __syncthreads();
    int nf = snc < 4096 ? snc : 4096;
    int S = (nf <= 2048) ? 2048 : 4096;
    __syncthreads();
    int half = S >> 1;
    for (int k = 2; k <= S; k <<= 1) {
        for (int j = k >> 1; j > 0; j >>= 1) {
            for (int t = tid; t < half; t += blockDim.x) {
                int i = ((t & ~(j - 1)) << 1) | (t & (j - 1));
                int p = i | j;
                unsigned long long va = sv[i], vb = sv[p];
                bool up = ((i & k) == 0);
                if (up ? (va < vb) : (va > vb)) { sv[i] = vb; sv[p] = va; }
            }
            __syncthreads();
        }
    }
    for (int r = tid; r < K_SEL; r += blockDim.x) {
        unsigned long long v = sv[r];
        unsigned int key = (unsigned int)(v >> 32);
        unsigned int idx = ~(unsigned int)(v & 0xFFFFFFFFu);
        g_validk[r] = (key != 0u) ? 1 : 0;
        float4 box = make_float4(0.f, 0.f, 0.f, 0.f);
        if (key != 0u) box = decode_box(anchors[idx], locs[idx]);
        g_boxes[r] = box;
    }
}

// -------- K5: suppression-edge extraction --------
__global__ void k_pairs() {
    int bi = blockIdx.y, bj = blockIdx.x;
    if (bi > bj) return;
    __shared__ float4 sb[64];
    int t = threadIdx.x;
    int ig = bi * 64 + t;
    sb[t] = (ig < K_SEL) ? g_boxes[ig] : make_float4(0.f, 0.f, 0.f, 0.f);
    __syncthreads();
    int j = bj * 64 + t;
    if (j >= K_SEL) return;
    float4 bb = g_boxes[j];
    float aj = (bb.z - bb.x) * (bb.w - bb.y);
    #pragma unroll 4
    for (int ii = 0; ii < 64; ii++) {
        int i = bi * 64 + ii;
        if (i >= j || i >= K_SEL) continue;
        float4 ba = sb[ii];
        float xx1 = fmaxf(ba.x, bb.x);
        float yy1 = fmaxf(ba.y, bb.y);
        float xx2 = fminf(ba.z, bb.z);
        float yy2 = fminf(ba.w, bb.w);
        float iw = fmaxf(xx2 - xx1, 0.0f);
        float ih = fmaxf(yy2 - yy1, 0.0f);
        float inter = iw * ih;
        float ai = (ba.z - ba.x) * (ba.w - ba.y);
        float u = fmaxf(ai + aj - inter, 1e-9f);
        if (inter / u > NMS_TH) {
            unsigned int pos = atomicAdd(&g_ctl[CTL_NPAIRS], 1u);
            g_pairs[pos] = ((unsigned)i << 11) | (unsigned)j;
        }
    }
}

// -------- K6: Jacobi greedy-NMS fixed point + compact + write output --------
__global__ void k_resolve(float* __restrict__ outf) {
    __shared__ unsigned char ka[K_SEL], kb[K_SEL];
    __shared__ int changed;
    __shared__ int psA[2048], psB[2048];
    int tid = threadIdx.x;
    int np = (int)g_ctl[CTL_NPAIRS];
    for (int j = tid; j < K_SEL; j += blockDim.x) ka[j] = g_validk[j];
    __syncthreads();
    for (int it = 0; it <= K_SEL; ++it) {
        if (tid == 0) changed = 0;
        for (int j = tid; j < K_SEL; j += blockDim.x) kb[j] = g_validk[j];
        __syncthreads();
        for (int p = tid; p < np; p += blockDim.x) {
            unsigned int pr = g_pairs[p];
            int i = (int)(pr >> 11), j = (int)(pr & 2047u);
            if (ka[i]) kb[j] = 0;
        }
        __syncthreads();
        for (int j = tid; j < K_SEL; j += blockDim.x) {
            if (kb[j] != ka[j]) { changed = 1; ka[j] = kb[j]; }
        }
        __syncthreads();
        int done = (changed == 0);
        __syncthreads();
        if (done) break;
    }
    for (int i = tid; i < 2048; i += blockDim.x) psA[i] = (i < K_SEL) ? (int)ka[i] : 0;
    __syncthreads();
    int* src = psA; int* dst = psB;
    for (int d = 1; d < 2048; d <<= 1) {
        for (int i = tid; i < 2048; i += blockDim.x)
            dst[i] = src[i] + (i >= d ? src[i - d] : 0);
        __syncthreads();
        int* t2 = src; src = dst; dst = t2;
    }
    float4* out4 = (float4*)outf;
    for (int r = tid; r < OUT_ROWS; r += blockDim.x)
        out4[r] = make_float4(0.f, 0.f, 0.f, 0.f);
    __syncthreads();
    for (int j = tid; j < K_SEL; j += blockDim.x) {
        if (ka[j]) {
            int pos = src[j] - 1;
            if (pos < OUT_ROWS) out4[pos] = g_boxes[j];
        }
    }
}

extern "C" void kernel_launch(void* const* d_in, const int* in_sizes, int n_in,
                              void* d_out, int out_size) {
    const float4* locs    = (const float4*)d_in[0];
    const float4* scores4 = (const float4*)d_in[1];
    const float4* anchors = (const float4*)d_in[2];
    float* out = (float*)d_out;

    k_zero<<<64, 256>>>();
    k_decode<<<(N_GRP + 255) / 256, 256>>>(locs, scores4, anchors);
    k_select<<<1, 1024>>>();
    k_collect<<<(N_GRP / 2 + 255) / 256, 256>>>();
    k_finalize<<<1, 1024>>>(locs, anchors);
    k_pairs<<<dim3(32, 32), 64>>>();
    k_resolve<<<1, 1024>>>(out);
}

// round 5
// speedup vs baseline: 1.3948x; 1.3948x over previous
#include <cuda_runtime.h>
#include <cuda_bf16.h>
#include <cstdint>

#define N_ANCH   2000000
#define K_SEL    2000
#define OUT_ROWS 1000
#define IMG_SZ   800.0f
#define MIN_SZ   16.0f
#define NMS_TH   0.7f

#define NFINE    4096
#define NCOARSE  65536
#define HI_CAP   262144
#define HI_LO    0.984375f          // 63/64

#define CTL_THRESH 0
#define CTL_FLAG   1
#define CTL_NHI    2
#define CTL_NCAND  3
#define CTL_NPAIRS 4

// -------- device scratch --------
__device__ unsigned int       g_hist_fine[NFINE];      // hi-region hist [63/64, 1)
__device__ unsigned int       g_hist_coarse[NCOARSE];  // fallback hist [0, 1)
__device__ unsigned int       g_ctl[16];
__device__ unsigned long long g_hi[HI_CAP];            // 2 MB hi-score staging
__device__ unsigned int       g_keys[N_ANCH];          // 8 MB (fallback path only)
__device__ unsigned long long g_cand[8192];
__device__ float4             g_boxes[K_SEL];
__device__ unsigned char      g_validk[K_SEL];
__device__ unsigned int       g_pairs[2000000];

// -------- decode helper (matches reference math) --------
__device__ __forceinline__ float4 decode_box(float4 a, float4 l) {
    float w  = a.z - a.x;
    float h  = a.w - a.y;
    float cx = a.x + 0.5f * w;
    float cy = a.y + 0.5f * h;
    float pcx = cx + l.x * w;
    float pcy = cy + l.y * h;
    float pw  = w * expf(l.z);
    float ph  = h * expf(l.w);
    float x1 = fminf(fmaxf(pcx - 0.5f * pw, 0.0f), IMG_SZ);
    float y1 = fminf(fmaxf(pcy - 0.5f * ph, 0.0f), IMG_SZ);
    float x2 = fminf(fmaxf(pcx + 0.5f * pw, 0.0f), IMG_SZ);
    float y2 = fminf(fmaxf(pcy + 0.5f * ph, 0.0f), IMG_SZ);
    return make_float4(x1, y1, x2, y2);
}

// -------- K0: zero hists + ctl --------
__global__ void k_zero() {
    int stride = gridDim.x * blockDim.x;
    for (int i = blockIdx.x * blockDim.x + threadIdx.x; i < NFINE + NCOARSE + 16; i += stride) {
        if (i < NFINE)                g_hist_fine[i] = 0u;
        else if (i < NFINE + NCOARSE) g_hist_coarse[i - NFINE] = 0u;
        else                          g_ctl[i - NFINE - NCOARSE] = 0u;
    }
}

// -------- K1: streaming decode; hi-score elements -> hi-list + fine hist --------
__global__ void __launch_bounds__(256) k_decode(const float4* __restrict__ locs,
                                                const float*  __restrict__ scores,
                                                const float4* __restrict__ anchors) {
    int i = blockIdx.x * blockDim.x + threadIdx.x;
    if (i >= N_ANCH) return;
    float4 a = anchors[i];
    float4 l = locs[i];
    float  s = scores[i];
    float4 d = decode_box(a, l);
    bool valid = (d.z - d.x >= MIN_SZ) && (d.w - d.y >= MIN_SZ);
    if (valid && s >= HI_LO) {
        unsigned int key = __float_as_uint(s) + 1u;
        int f = (int)(s * 262144.0f) - 258048;
        if (f > NFINE - 1) f = NFINE - 1;
        float lo = (float)(258048 + f) * (1.0f / 262144.0f);   // exact
        if (s < lo) f--;                                        // rounding guard
        if (f >= 0) {
            atomicAdd(&g_hist_fine[f], 1u);
            unsigned int pos = atomicAdd(&g_ctl[CTL_NHI], 1u);
            if (pos < HI_CAP)
                g_hi[pos] = ((unsigned long long)key << 32) | (unsigned int)(~(unsigned)i);
        }
    }
}

// -------- K2: hi-region select; sets THRESH or FLAG=1 (fallback) --------
__global__ void k_selA() {
    __shared__ unsigned int A[1024], B[1024];
    int t = threadIdx.x;
    const unsigned int* h = &g_hist_fine[t * 4];
    A[t] = h[0] + h[1] + h[2] + h[3];
    __syncthreads();
    unsigned int* src = A; unsigned int* dst = B;
    for (int d = 1; d < 1024; d <<= 1) {
        dst[t] = src[t] + (t + d < 1024 ? src[t + d] : 0u);
        __syncthreads();
        unsigned int* tmp = src; src = dst; dst = tmp;
    }
    unsigned int total = src[0];
    unsigned int nhi   = g_ctl[CTL_NHI];
    bool ok = (total >= (unsigned)K_SEL) && (nhi <= (unsigned)HI_CAP);
    if (t == 0 && !ok) g_ctl[CTL_FLAG] = 1u;
    if (ok) {
        unsigned int suf  = src[t];
        unsigned int sufN = (t == 1023) ? 0u : src[t + 1];
        if (suf >= (unsigned)K_SEL && sufN < (unsigned)K_SEL) {
            unsigned int running = sufN;
            for (int i = 3; i >= 0; i--) {
                running += h[i];
                if (running >= (unsigned)K_SEL) {
                    int b = t * 4 + i;
                    g_ctl[CTL_THRESH] =
                        __float_as_uint((float)(258048 + b) * (1.0f / 262144.0f)) + 1u;
                    break;
                }
            }
        }
    }
}

// -------- K3 (fallback only): full decode -> keys + coarse hist --------
__global__ void __launch_bounds__(256) k_decode_fb(const float4* __restrict__ locs,
                                                   const float*  __restrict__ scores,
                                                   const float4* __restrict__ anchors) {
    if (g_ctl[CTL_FLAG] == 0u) return;
    int stride = gridDim.x * blockDim.x;
    for (int i = blockIdx.x * blockDim.x + threadIdx.x; i < N_ANCH; i += stride) {
        float4 a = anchors[i];
        float4 l = locs[i];
        float  s = scores[i];
        float4 d = decode_box(a, l);
        bool valid = (d.z - d.x >= MIN_SZ) && (d.w - d.y >= MIN_SZ);
        unsigned int key = valid ? (__float_as_uint(s) + 1u) : 0u;
        g_keys[i] = key;
        if (key) {
            float sc = fmaxf(s, 0.0f);
            int b = (int)(sc * 65536.0f);
            if (b > NCOARSE - 1) b = NCOARSE - 1;
            float lo = (float)b * (1.0f / 65536.0f);
            if (sc < lo) b--;
            if (b < 0) b = 0;
            atomicAdd(&g_hist_coarse[b], 1u);
        }
    }
}

// -------- K4 (fallback only): coarse select --------
__global__ void k_selB() {
    if (g_ctl[CTL_FLAG] == 0u) return;
    __shared__ unsigned int A[1024], B[1024];
    int t = threadIdx.x;
    const unsigned int* h = &g_hist_coarse[t * 64];
    unsigned int s = 0;
    #pragma unroll 8
    for (int i = 0; i < 64; i++) s += h[i];
    A[t] = s;
    __syncthreads();
    unsigned int* src = A; unsigned int* dst = B;
    for (int d = 1; d < 1024; d <<= 1) {
        dst[t] = src[t] + (t + d < 1024 ? src[t + d] : 0u);
        __syncthreads();
        unsigned int* tmp = src; src = dst; dst = tmp;
    }
    unsigned int total = src[0];
    if (total < (unsigned)K_SEL) {
        if (t == 0) g_ctl[CTL_THRESH] = 1u;     // take every valid key
        return;
    }
    unsigned int suf  = src[t];
    unsigned int sufN = (t == 1023) ? 0u : src[t + 1];
    if (suf >= (unsigned)K_SEL && sufN < (unsigned)K_SEL) {
        unsigned int running = sufN;
        for (int i = 63; i >= 0; i--) {
            running += h[i];
            if (running >= (unsigned)K_SEL) {
                int b = t * 64 + i;
                g_ctl[CTL_THRESH] =
                    __float_as_uint((float)b * (1.0f / 65536.0f)) + 1u;
                break;
            }
        }
    }
}

// -------- K5: collect candidates >= THRESH --------
__global__ void __launch_bounds__(256) k_collect() {
    unsigned int flag = g_ctl[CTL_FLAG];
    unsigned int T    = g_ctl[CTL_THRESH];
    int stride = gridDim.x * blockDim.x;
    if (flag == 0u) {
        unsigned int n = g_ctl[CTL_NHI];
        if (n > (unsigned)HI_CAP) n = HI_CAP;
        for (int i = blockIdx.x * blockDim.x + threadIdx.x; i < (int)n; i += stride) {
            unsigned long long v = g_hi[i];
            if ((unsigned int)(v >> 32) >= T) {
                unsigned int pos = atomicAdd(&g_ctl[CTL_NCAND], 1u);
                if (pos < 8192u) g_cand[pos] = v;
            }
        }
    } else {
        for (int i = blockIdx.x * blockDim.x + threadIdx.x; i < N_ANCH; i += stride) {
            unsigned int key = g_keys[i];
            if (key >= T) {
                unsigned int pos = atomicAdd(&g_ctl[CTL_NCAND], 1u);
                if (pos < 8192u)
                    g_cand[pos] = ((unsigned long long)key << 32) | (unsigned int)(~(unsigned)i);
            }
        }
    }
}

// -------- K6: sort candidates (adaptive 2048/4096), build top-2000 boxes --------
__global__ void k_finalize(const float4* __restrict__ locs,
                           const float4* __restrict__ anchors) {
    __shared__ unsigned long long sv[4096];
    int tid = threadIdx.x;
    unsigned int n = g_ctl[CTL_NCAND];
    if (n > 8192u) n = 8192u;
    unsigned int nf = n > 4096u ? 4096u : n;
    int S = (nf <= 2048u) ? 2048 : 4096;
    for (int i = tid; i < S; i += blockDim.x)
        sv[i] = (i < (int)nf) ? g_cand[i] : 0ULL;
    __syncthreads();
    int half = S >> 1;
    for (int k = 2; k <= S; k <<= 1) {
        for (int j = k >> 1; j > 0; j >>= 1) {
            for (int t = tid; t < half; t += blockDim.x) {
                int i = ((t & ~(j - 1)) << 1) | (t & (j - 1));
                int p = i | j;
                unsigned long long va = sv[i], vb = sv[p];
                bool up = ((i & k) == 0);
                if (up ? (va < vb) : (va > vb)) { sv[i] = vb; sv[p] = va; }
            }
            __syncthreads();
        }
    }
    for (int r = tid; r < K_SEL; r += blockDim.x) {
        unsigned long long v = sv[r];
        unsigned int key = (unsigned int)(v >> 32);
        unsigned int idx = ~(unsigned int)(v & 0xFFFFFFFFu);
        g_validk[r] = (key != 0u) ? 1 : 0;
        float4 box = make_float4(0.f, 0.f, 0.f, 0.f);
        if (key != 0u) box = decode_box(anchors[idx], locs[idx]);
        g_boxes[r] = box;
    }
}

// -------- K7: suppression-edge extraction --------
__global__ void k_pairs() {
    int bi = blockIdx.y, bj = blockIdx.x;
    if (bi > bj) return;
    __shared__ float4 sb[64];
    int t = threadIdx.x;
    int ig = bi * 64 + t;
    sb[t] = (ig < K_SEL) ? g_boxes[ig] : make_float4(0.f, 0.f, 0.f, 0.f);
    __syncthreads();
    int j = bj * 64 + t;
    if (j >= K_SEL) return;
    float4 bb = g_boxes[j];
    float aj = (bb.z - bb.x) * (bb.w - bb.y);
    #pragma unroll 4
    for (int ii = 0; ii < 64; ii++) {
        int i = bi * 64 + ii;
        if (i >= j || i >= K_SEL) continue;
        float4 ba = sb[ii];
        float xx1 = fmaxf(ba.x, bb.x);
        float yy1 = fmaxf(ba.y, bb.y);
        float xx2 = fminf(ba.z, bb.z);
        float yy2 = fminf(ba.w, bb.w);
        float iw = fmaxf(xx2 - xx1, 0.0f);
        float ih = fmaxf(yy2 - yy1, 0.0f);
        float inter = iw * ih;
        float ai = (ba.z - ba.x) * (ba.w - ba.y);
        float u = fmaxf(ai + aj - inter, 1e-9f);
        if (inter / u > NMS_TH) {
            unsigned int pos = atomicAdd(&g_ctl[CTL_NPAIRS], 1u);
            g_pairs[pos] = ((unsigned)i << 11) | (unsigned)j;
        }
    }
}

// -------- K8: Jacobi greedy-NMS fixed point + compact + write output --------
__global__ void k_resolve(float* __restrict__ outf) {
    __shared__ unsigned char ka[K_SEL], kb[K_SEL];
    __shared__ int changed;
    __shared__ int psA[2048], psB[2048];
    int tid = threadIdx.x;
    int np = (int)g_ctl[CTL_NPAIRS];
    for (int j = tid; j < K_SEL; j += blockDim.x) ka[j] = g_validk[j];
    __syncthreads();
    for (int it = 0; it <= K_SEL; ++it) {
        if (tid == 0) changed = 0;
        for (int j = tid; j < K_SEL; j += blockDim.x) kb[j] = g_validk[j];
        __syncthreads();
        for (int p = tid; p < np; p += blockDim.x) {
            unsigned int pr = g_pairs[p];
            int i = (int)(pr >> 11), j = (int)(pr & 2047u);
            if (ka[i]) kb[j] = 0;
        }
        __syncthreads();
        for (int j = tid; j < K_SEL; j += blockDim.x) {
            if (kb[j] != ka[j]) { changed = 1; ka[j] = kb[j]; }
        }
        __syncthreads();
        int done = (changed == 0);
        __syncthreads();
        if (done) break;
    }
    for (int i = tid; i < 2048; i += blockDim.x) psA[i] = (i < K_SEL) ? (int)ka[i] : 0;
    __syncthreads();
    int* src = psA; int* dst = psB;
    for (int d = 1; d < 2048; d <<= 1) {
        for (int i = tid; i < 2048; i += blockDim.x)
            dst[i] = src[i] + (i >= d ? src[i - d] : 0);
        __syncthreads();
        int* t2 = src; src = dst; dst = t2;
    }
    float4* out4 = (float4*)outf;
    for (int r = tid; r < OUT_ROWS; r += blockDim.x)
        out4[r] = make_float4(0.f, 0.f, 0.f, 0.f);
    __syncthreads();
    for (int j = tid; j < K_SEL; j += blockDim.x) {
        if (ka[j]) {
            int pos = src[j] - 1;
            if (pos < OUT_ROWS) out4[pos] = g_boxes[j];
        }
    }
}

extern "C" void kernel_launch(void* const* d_in, const int* in_sizes, int n_in,
                              void* d_out, int out_size) {
    const float4* locs    = (const float4*)d_in[0];
    const float*  scores  = (const float*) d_in[1];
    const float4* anchors = (const float4*)d_in[2];
    float* out = (float*)d_out;

    k_zero<<<96, 256>>>();
    k_decode<<<(N_ANCH + 255) / 256, 256>>>(locs, scores, anchors);
    k_selA<<<1, 1024>>>();
    k_decode_fb<<<592, 256>>>(locs, scores, anchors);
    k_selB<<<1, 1024>>>();
    k_collect<<<128, 256>>>();
    k_finalize<<<1, 1024>>>(locs, anchors);
    k_pairs<<<dim3(32, 32), 64>>>();
    k_resolve<<<1, 1024>>>(out);
}

// round 6
// speedup vs baseline: 1.5049x; 1.0789x over previous
#include <cuda_runtime.h>
#include <cuda_bf16.h>
#include <cstdint>

#define N_ANCH   2000000
#define N_GRP    (N_ANCH / 4)
#define K_SEL    2000
#define OUT_ROWS 1000
#define IMG_SZ   800.0f
#define MIN_SZ   16.0f
#define NMS_TH   0.7f

#define NFINE    4096
#define NCOARSE  65536
#define HI_CAP   262144
#define HI_LO    0.984375f          // 63/64
#define STAGE_CAP 1024

#define CTL_FLAG   0
#define CTL_NHI    1
#define CTL_NPAIRS 2

// -------- device scratch --------
__device__ unsigned int       g_hist_fine[NFINE];
__device__ unsigned int       g_hist_coarse[NCOARSE];
__device__ unsigned int       g_ctl[16];
__device__ unsigned long long g_hi[HI_CAP];
__device__ unsigned int       g_keys[N_ANCH];          // fallback only
__device__ float4             g_boxes[K_SEL];
__device__ unsigned char      g_validk[K_SEL];
__device__ unsigned int       g_pairs[2000000];

// -------- decode helper (matches reference math) --------
__device__ __forceinline__ float4 decode_box(float4 a, float4 l) {
    float w  = a.z - a.x;
    float h  = a.w - a.y;
    float cx = a.x + 0.5f * w;
    float cy = a.y + 0.5f * h;
    float pcx = cx + l.x * w;
    float pcy = cy + l.y * h;
    float pw  = w * expf(l.z);
    float ph  = h * expf(l.w);
    float x1 = fminf(fmaxf(pcx - 0.5f * pw, 0.0f), IMG_SZ);
    float y1 = fminf(fmaxf(pcy - 0.5f * ph, 0.0f), IMG_SZ);
    float x2 = fminf(fmaxf(pcx + 0.5f * pw, 0.0f), IMG_SZ);
    float y2 = fminf(fmaxf(pcy + 0.5f * ph, 0.0f), IMG_SZ);
    return make_float4(x1, y1, x2, y2);
}

// -------- K0: zero hists + ctl --------
__global__ void k_zero() {
    int stride = gridDim.x * blockDim.x;
    for (int i = blockIdx.x * blockDim.x + threadIdx.x; i < NFINE + NCOARSE + 16; i += stride) {
        if (i < NFINE)                g_hist_fine[i] = 0u;
        else if (i < NFINE + NCOARSE) g_hist_coarse[i - NFINE] = 0u;
        else                          g_ctl[i - NFINE - NCOARSE] = 0u;
    }
}

// -------- K1: score scan; sparse decode of hi-score elements --------
__global__ void __launch_bounds__(256) k_scan(const float4* __restrict__ locs,
                                              const float4* __restrict__ scores4,
                                              const float4* __restrict__ anchors) {
    __shared__ unsigned long long stage[STAGE_CAP];
    __shared__ int s_cnt;
    __shared__ unsigned int s_base;
    if (threadIdx.x == 0) s_cnt = 0;
    __syncthreads();

    int base = blockIdx.x * blockDim.x * 4 + threadIdx.x;    // float4 index
    float4 sv[4];
    int   gi[4];
    #pragma unroll
    for (int j = 0; j < 4; j++) {
        gi[j] = base + j * 256;
        sv[j] = (gi[j] < N_GRP) ? scores4[gi[j]] : make_float4(0.f, 0.f, 0.f, 0.f);
    }
    #pragma unroll
    for (int j = 0; j < 4; j++) {
        if (gi[j] >= N_GRP) continue;
        #pragma unroll
        for (int c = 0; c < 4; c++) {
            float s = (c == 0) ? sv[j].x : (c == 1) ? sv[j].y : (c == 2) ? sv[j].z : sv[j].w;
            if (s >= HI_LO) {
                int i = 4 * gi[j] + c;
                float4 d = decode_box(anchors[i], locs[i]);
                bool valid = (d.z - d.x >= MIN_SZ) && (d.w - d.y >= MIN_SZ);
                if (valid) {
                    int f = (int)(s * 262144.0f) - 258048;
                    if (f > NFINE - 1) f = NFINE - 1;
                    float lo = (float)(258048 + f) * (1.0f / 262144.0f);
                    if (s < lo) f--;
                    if (f >= 0) {
                        atomicAdd(&g_hist_fine[f], 1u);
                        unsigned int key = __float_as_uint(s) + 1u;
                        int p = atomicAdd(&s_cnt, 1);
                        if (p < STAGE_CAP)
                            stage[p] = ((unsigned long long)key << 32) | (unsigned int)(~(unsigned)i);
                        else
                            g_ctl[CTL_FLAG] = 1u;
                    }
                }
            }
        }
    }
    __syncthreads();
    int cnt = s_cnt;
    if (cnt > STAGE_CAP) cnt = STAGE_CAP;
    if (threadIdx.x == 0 && cnt > 0)
        s_base = atomicAdd(&g_ctl[CTL_NHI], (unsigned)cnt);
    __syncthreads();
    if (cnt > 0) {
        unsigned int b = s_base;
        for (int p = threadIdx.x; p < cnt; p += 256)
            if (b + p < (unsigned)HI_CAP) g_hi[b + p] = stage[p];
            else g_ctl[CTL_FLAG] = 1u;
    }
}

// -------- K2: fused select + collect + sort + build top-2000 boxes --------
__global__ void k_top(const float4* __restrict__ locs,
                      const float4* __restrict__ anchors) {
    __shared__ unsigned int A[1024], B[1024];
    __shared__ unsigned long long sv[4096];
    __shared__ int s_nc;
    __shared__ unsigned int s_T;
    int t = threadIdx.x;
    if (g_ctl[CTL_FLAG]) return;                       // uniform

    const unsigned int* h = &g_hist_fine[t * 4];
    A[t] = h[0] + h[1] + h[2] + h[3];
    __syncthreads();
    unsigned int* src = A; unsigned int* dst = B;
    for (int d = 1; d < 1024; d <<= 1) {
        dst[t] = src[t] + (t + d < 1024 ? src[t + d] : 0u);
        __syncthreads();
        unsigned int* tmp = src; src = dst; dst = tmp;
    }
    unsigned int total = src[0];
    unsigned int nhi   = g_ctl[CTL_NHI];
    if (total < (unsigned)K_SEL || nhi > (unsigned)HI_CAP) {
        if (t == 0) g_ctl[CTL_FLAG] = 1u;
        return;                                        // uniform
    }
    unsigned int suf  = src[t];
    unsigned int sufN = (t == 1023) ? 0u : src[t + 1];
    if (suf >= (unsigned)K_SEL && sufN < (unsigned)K_SEL) {
        unsigned int running = sufN;
        for (int i = 3; i >= 0; i--) {
            running += h[i];
            if (running >= (unsigned)K_SEL) {
                s_T = __float_as_uint((float)(258048 + t * 4 + i) * (1.0f / 262144.0f)) + 1u;
                break;
            }
        }
    }
    if (t == 0) s_nc = 0;
    __syncthreads();
    unsigned int T = s_T;

    for (int i = t; i < (int)nhi; i += 1024) {
        unsigned long long v = g_hi[i];
        if ((unsigned int)(v >> 32) >= T) {
            int p = atomicAdd(&s_nc, 1);
            if (p < 4096) sv[p] = v;
        }
    }
    __syncthreads();
    int nc = s_nc;
    if (nc > 4096) {
        if (t == 0) g_ctl[CTL_FLAG] = 1u;
        return;                                        // uniform
    }
    int S = (nc <= 2048) ? 2048 : 4096;
    for (int i = nc + t; i < S; i += 1024) sv[i] = 0ULL;
    __syncthreads();
    int half = S >> 1;
    for (int k = 2; k <= S; k <<= 1) {
        for (int j = k >> 1; j > 0; j >>= 1) {
            for (int w = t; w < half; w += 1024) {
                int i = ((w & ~(j - 1)) << 1) | (w & (j - 1));
                int p = i | j;
                unsigned long long va = sv[i], vb = sv[p];
                bool up = ((i & k) == 0);
                if (up ? (va < vb) : (va > vb)) { sv[i] = vb; sv[p] = va; }
            }
            __syncthreads();
        }
    }
    for (int r = t; r < K_SEL; r += 1024) {
        unsigned long long v = sv[r];
        unsigned int key = (unsigned int)(v >> 32);
        unsigned int idx = ~(unsigned int)(v & 0xFFFFFFFFu);
        g_validk[r] = (key != 0u) ? 1 : 0;
        float4 box = make_float4(0.f, 0.f, 0.f, 0.f);
        if (key != 0u) box = decode_box(anchors[idx], locs[idx]);
        g_boxes[r] = box;
    }
}

// -------- K3 (fallback only): full decode -> keys + coarse hist --------
__global__ void __launch_bounds__(256) k_decode_fb(const float4* __restrict__ locs,
                                                   const float*  __restrict__ scores,
                                                   const float4* __restrict__ anchors) {
    if (g_ctl[CTL_FLAG] == 0u) return;
    int stride = gridDim.x * blockDim.x;
    for (int i = blockIdx.x * blockDim.x + threadIdx.x; i < N_ANCH; i += stride) {
        float4 d = decode_box(anchors[i], locs[i]);
        float  s = scores[i];
        bool valid = (d.z - d.x >= MIN_SZ) && (d.w - d.y >= MIN_SZ);
        unsigned int key = valid ? (__float_as_uint(s) + 1u) : 0u;
        g_keys[i] = key;
        if (key) {
            float sc = fmaxf(s, 0.0f);
            int b = (int)(sc * 65536.0f);
            if (b > NCOARSE - 1) b = NCOARSE - 1;
            float lo = (float)b * (1.0f / 65536.0f);
            if (sc < lo) b--;
            if (b < 0) b = 0;
            atomicAdd(&g_hist_coarse[b], 1u);
        }
    }
}

// -------- K4 (fallback only): select + collect + sort + boxes --------
__global__ void k_fb_tail(const float4* __restrict__ locs,
                          const float4* __restrict__ anchors) {
    if (g_ctl[CTL_FLAG] == 0u) return;
    __shared__ unsigned int A[1024], B[1024];
    __shared__ unsigned long long sv[4096];
    __shared__ int s_nc;
    __shared__ unsigned int s_T;
    int t = threadIdx.x;

    const unsigned int* h = &g_hist_coarse[t * 64];
    unsigned int s = 0;
    #pragma unroll 8
    for (int i = 0; i < 64; i++) s += h[i];
    A[t] = s;
    __syncthreads();
    unsigned int* src = A; unsigned int* dst = B;
    for (int d = 1; d < 1024; d <<= 1) {
        dst[t] = src[t] + (t + d < 1024 ? src[t + d] : 0u);
        __syncthreads();
        unsigned int* tmp = src; src = dst; dst = tmp;
    }
    unsigned int total = src[0];
    if (t == 0) s_T = 1u;                       // default: every valid key
    __syncthreads();
    if (total >= (unsigned)K_SEL) {
        unsigned int suf  = src[t];
        unsigned int sufN = (t == 1023) ? 0u : src[t + 1];
        if (suf >= (unsigned)K_SEL && sufN < (unsigned)K_SEL) {
            unsigned int running = sufN;
            for (int i = 63; i >= 0; i--) {
                running += h[i];
                if (running >= (unsigned)K_SEL) {
                    s_T = __float_as_uint((float)(t * 64 + i) * (1.0f / 65536.0f)) + 1u;
                    break;
                }
            }
        }
    }
    if (t == 0) s_nc = 0;
    __syncthreads();
    unsigned int T = s_T;
    for (int i = t; i < N_ANCH; i += 1024) {
        unsigned int key = g_keys[i];
        if (key >= T) {
            int p = atomicAdd(&s_nc, 1);
            if (p < 4096)
                sv[p] = ((unsigned long long)key << 32) | (unsigned int)(~(unsigned)i);
        }
    }
    __syncthreads();
    int nc = s_nc; if (nc > 4096) nc = 4096;
    int S = (nc <= 2048) ? 2048 : 4096;
    for (int i = nc + t; i < S; i += 1024) sv[i] = 0ULL;
    __syncthreads();
    int half = S >> 1;
    for (int k = 2; k <= S; k <<= 1) {
        for (int j = k >> 1; j > 0; j >>= 1) {
            for (int w = t; w < half; w += 1024) {
                int i = ((w & ~(j - 1)) << 1) | (w & (j - 1));
                int p = i | j;
                unsigned long long va = sv[i], vb = sv[p];
                bool up = ((i & k) == 0);
                if (up ? (va < vb) : (va > vb)) { sv[i] = vb; sv[p] = va; }
            }
            __syncthreads();
        }
    }
    for (int r = t; r < K_SEL; r += 1024) {
        unsigned long long v = sv[r];
        unsigned int key = (unsigned int)(v >> 32);
        unsigned int idx = ~(unsigned int)(v & 0xFFFFFFFFu);
        g_validk[r] = (key != 0u) ? 1 : 0;
        float4 box = make_float4(0.f, 0.f, 0.f, 0.f);
        if (key != 0u) box = decode_box(anchors[idx], locs[idx]);
        g_boxes[r] = box;
    }
}

// -------- K5: suppression-edge extraction (warp-aggregated emit) --------
__global__ void k_pairs() {
    int bi = blockIdx.y, bj = blockIdx.x;
    if (bi > bj) return;
    __shared__ float4 sb[64];
    int t = threadIdx.x;
    int lane = t & 31;
    int ig = bi * 64 + t;
    sb[t] = (ig < K_SEL) ? g_boxes[ig] : make_float4(0.f, 0.f, 0.f, 0.f);
    __syncthreads();
    int j = bj * 64 + t;
    bool okj = (j < K_SEL);
    float4 bb = okj ? g_boxes[j] : make_float4(0.f, 0.f, 0.f, 0.f);
    float aj = (bb.z - bb.x) * (bb.w - bb.y);
    for (int ii = 0; ii < 64; ii++) {
        int i = bi * 64 + ii;
        bool hit = false;
        if (okj && i < j && i < K_SEL) {
            float4 ba = sb[ii];
            float xx1 = fmaxf(ba.x, bb.x);
            float yy1 = fmaxf(ba.y, bb.y);
            float xx2 = fminf(ba.z, bb.z);
            float yy2 = fminf(ba.w, bb.w);
            float iw = fmaxf(xx2 - xx1, 0.0f);
            float ih = fmaxf(yy2 - yy1, 0.0f);
            float inter = iw * ih;
            float ai = (ba.z - ba.x) * (ba.w - ba.y);
            float u = fmaxf(ai + aj - inter, 1e-9f);
            hit = (inter / u > NMS_TH);
        }
        unsigned int mask = __ballot_sync(0xFFFFFFFFu, hit);
        if (mask) {
            int leader = __ffs(mask) - 1;
            unsigned int basep = 0;
            if (lane == leader)
                basep = atomicAdd(&g_ctl[CTL_NPAIRS], (unsigned)__popc(mask));
            basep = __shfl_sync(0xFFFFFFFFu, basep, leader);
            if (hit) {
                int rank = __popc(mask & ((1u << lane) - 1u));
                g_pairs[basep + rank] = ((unsigned)i << 11) | (unsigned)j;
            }
        }
    }
}

// -------- K6: Jacobi greedy-NMS fixed point + compact + write output --------
__global__ void k_resolve(float* __restrict__ outf) {
    __shared__ unsigned char ka[K_SEL], kb[K_SEL];
    __shared__ int changed;
    __shared__ int psA[2048], psB[2048];
    int tid = threadIdx.x;
    int np = (int)g_ctl[CTL_NPAIRS];
    for (int j = tid; j < K_SEL; j += blockDim.x) ka[j] = g_validk[j];
    __syncthreads();
    for (int it = 0; it <= K_SEL; ++it) {
        if (tid == 0) changed = 0;
        for (int j = tid; j < K_SEL; j += blockDim.x) kb[j] = g_validk[j];
        __syncthreads();
        for (int p = tid; p < np; p += blockDim.x) {
            unsigned int pr = g_pairs[p];
            int i = (int)(pr >> 11), j = (int)(pr & 2047u);
            if (ka[i]) kb[j] = 0;
        }
        __syncthreads();
        for (int j = tid; j < K_SEL; j += blockDim.x) {
            if (kb[j] != ka[j]) { changed = 1; ka[j] = kb[j]; }
        }
        __syncthreads();
        int done = (changed == 0);
        __syncthreads();
        if (done) break;
    }
    for (int i = tid; i < 2048; i += blockDim.x) psA[i] = (i < K_SEL) ? (int)ka[i] : 0;
    __syncthreads();
    int* src = psA; int* dst = psB;
    for (int d = 1; d < 2048; d <<= 1) {
        for (int i = tid; i < 2048; i += blockDim.x)
            dst[i] = src[i] + (i >= d ? src[i - d] : 0);
        __syncthreads();
        int* t2 = src; src = dst; dst = t2;
    }
    float4* out4 = (float4*)outf;
    for (int r = tid; r < OUT_ROWS; r += blockDim.x)
        out4[r] = make_float4(0.f, 0.f, 0.f, 0.f);
    __syncthreads();
    for (int j = tid; j < K_SEL; j += blockDim.x) {
        if (ka[j]) {
            int pos = src[j] - 1;
            if (pos < OUT_ROWS) out4[pos] = g_boxes[j];
        }
    }
}

extern "C" void kernel_launch(void* const* d_in, const int* in_sizes, int n_in,
                              void* d_out, int out_size) {
    const float4* locs    = (const float4*)d_in[0];
    const float*  scores  = (const float*) d_in[1];
    const float4* scores4 = (const float4*)d_in[1];
    const float4* anchors = (const float4*)d_in[2];
    float* out = (float*)d_out;

    k_zero<<<96, 256>>>();
    k_scan<<<(N_GRP + 1023) / 1024, 256>>>(locs, scores4, anchors);
    k_top<<<1, 1024>>>(locs, anchors);
    k_decode_fb<<<148, 256>>>(locs, scores, anchors);
    k_fb_tail<<<1, 1024>>>(locs, anchors);
    k_pairs<<<dim3(32, 32), 64>>>();
    k_resolve<<<1, 1024>>>(out);
}